// round 15
// baseline (speedup 1.0000x reference)
#include <cuda_runtime.h>
#include <math.h>

// Hessian_49160195670508: x [16,3,1024,1024] f32, to_gray [3] -> out [16,1024,1024]
// gray -> 5x5 gaussian blur (SAME, zero pad) -> jnp.gradient Hessian ->
// 2x2 symmetric eig -> per-batch gamma = max(s)/2 -> Frangi-like response.

#define HH 1024
#define WW 1024
#define BB 16
#define NPIX ((size_t)HH * WW)

// Static device scratch (no cudaMalloc anywhere)
__device__ float g_blur[(size_t)BB * HH * WW];   // 64 MiB blurred gray
__device__ float g_pmax[BB * 1024];              // per-block partial max of s^2
__device__ float g_gamma[BB];                    // per-batch gamma

// ---------------------------------------------------------------------------
// Generic (edge-correct) jnp.gradient stencil over a blurred tile sg[36][44]
// whose element [r][c] is blur(by-2+r, bx-4+c). Only c in 2..37 is valid;
// formula selection by GLOBAL index guarantees invalid cells are never read.
// ---------------------------------------------------------------------------
__device__ __forceinline__ float sgx(const float (*sg)[44], int li, int lj, int gi)
{
    if (gi == 0)      return sg[li + 1][lj] - sg[li][lj];
    if (gi == HH - 1) return sg[li][lj] - sg[li - 1][lj];
    return 0.5f * (sg[li + 1][lj] - sg[li - 1][lj]);
}

__device__ __forceinline__ float sgy(const float (*sg)[44], int li, int lj, int gj)
{
    if (gj == 0)      return sg[li][lj + 1] - sg[li][lj];
    if (gj == WW - 1) return sg[li][lj] - sg[li][lj - 1];
    return 0.5f * (sg[li][lj + 1] - sg[li][lj - 1]);
}

__device__ __forceinline__ void hess_generic(const float (*sg)[44], int li, int lj,
                                             int gi, int gj,
                                             float& h00, float& h01, float& h11)
{
    if (gi == 0)           h00 = sgx(sg, li + 1, lj, 1) - sgx(sg, li, lj, 0);
    else if (gi == HH - 1) h00 = sgx(sg, li, lj, HH - 1) - sgx(sg, li - 1, lj, HH - 2);
    else                   h00 = 0.5f * (sgx(sg, li + 1, lj, gi + 1) - sgx(sg, li - 1, lj, gi - 1));

    if (gj == 0)           h01 = sgx(sg, li, lj + 1, gi) - sgx(sg, li, lj, gi);
    else if (gj == WW - 1) h01 = sgx(sg, li, lj, gi) - sgx(sg, li, lj - 1, gi);
    else                   h01 = 0.5f * (sgx(sg, li, lj + 1, gi) - sgx(sg, li, lj - 1, gi));

    if (gj == 0)           h11 = sgy(sg, li, lj + 1, 1) - sgy(sg, li, lj, 0);
    else if (gj == WW - 1) h11 = sgy(sg, li, lj, WW - 1) - sgy(sg, li, lj - 1, WW - 2);
    else                   h11 = 0.5f * (sgy(sg, li, lj + 1, gj + 1) - sgy(sg, li, lj - 1, gj - 1));
}

// Fast interior stencil: pure central 2nd differences, 4 consecutive rows
// per thread with register-cached columns.
__device__ __forceinline__ void hess4_fast(const float (*sg)[44], int r0, int lj,
                                           float* h00, float* h01, float* h11)
{
    float v[8], a[6], bc[6], cl[4], cr[4];
    #pragma unroll
    for (int t = 0; t < 8; t++) v[t] = sg[r0 + t][lj];
    #pragma unroll
    for (int t = 0; t < 6; t++) { a[t]  = sg[r0 + 1 + t][lj - 1];
                                  bc[t] = sg[r0 + 1 + t][lj + 1]; }
    #pragma unroll
    for (int t = 0; t < 4; t++) { cl[t] = sg[r0 + 2 + t][lj - 2];
                                  cr[t] = sg[r0 + 2 + t][lj + 2]; }
    #pragma unroll
    for (int k = 0; k < 4; k++) {
        h00[k] = 0.25f * (v[k] + v[k + 4]) - 0.5f * v[k + 2];
        h01[k] = 0.25f * ((bc[k + 2] - a[k + 2]) - (bc[k] - a[k]));
        h11[k] = 0.25f * (cl[k] + cr[k]) - 0.5f * v[k + 2];
    }
}

// ---------------------------------------------------------------------------
// Kernel 1 (FUSED): grayscale + separable 5x5 blur + write g_blur + per-block
// max of s^2 -- the blurred tile never leaves shared memory for the stencil.
// Gray halo: rows by-4..by+35, cols bx-4..bx+35 (zero pad outside image).
// Blurred tile sb[36][44]: [r][c] = blur(by-2+r, bx-4+c), valid c in 2..37.
// ---------------------------------------------------------------------------
__global__ __launch_bounds__(256) void k_blur_smax(
    const float* __restrict__ x, const float* __restrict__ tg,
    float w0, float w1, float w2)
{
    __shared__ float sgr[40][44];  // gray, rows by-4.., cols bx-4..bx+35
    __shared__ float sh[40][37];   // horiz blurred, cols bx-2..bx+33
    __shared__ float sb[36][44];   // fully blurred, rows by-2.., cols base bx-4
    __shared__ float red[8];

    const int b  = blockIdx.z;
    const int bx = blockIdx.x * 32;
    const int by = blockIdx.y * 32;
    const int tx = threadIdx.x, ty = threadIdx.y;
    const int tid = ty * 32 + tx;

    const float c0 = __ldg(tg + 0);
    const float c1 = __ldg(tg + 1);
    const float c2 = __ldg(tg + 2);
    const float* xb = x + (size_t)b * 3 * NPIX;

    const bool xedge = (blockIdx.x == 0) || (blockIdx.x == (WW / 32 - 1));
    const bool edge  = xedge || (blockIdx.y == 0) || (blockIdx.y == (HH / 32 - 1));

    // ---- load gray halo (zero outside image: SAME conv zero-pads) ----
    if (!xedge) {
        for (int idx = tid; idx < 400; idx += 256) {
            int r  = idx / 10;
            int c4 = (idx - r * 10) * 4;
            int hh = by + r - 4;
            float4 g4 = make_float4(0.f, 0.f, 0.f, 0.f);
            if (hh >= 0 && hh < HH) {
                size_t o = (size_t)hh * WW + (bx - 4) + c4;
                float4 a = *(const float4*)(xb + o);
                float4 v = *(const float4*)(xb + NPIX + o);
                float4 w = *(const float4*)(xb + 2 * NPIX + o);
                g4.x = c0 * a.x + c1 * v.x + c2 * w.x;
                g4.y = c0 * a.y + c1 * v.y + c2 * w.y;
                g4.z = c0 * a.z + c1 * v.z + c2 * w.z;
                g4.w = c0 * a.w + c1 * v.w + c2 * w.w;
            }
            *(float4*)&sgr[r][c4] = g4;
        }
    } else {
        for (int idx = tid; idx < 1600; idx += 256) {
            int r  = idx / 40;
            int c  = idx - r * 40;
            int hh = by + r - 4;
            int wc = bx - 4 + c;
            float v = 0.f;
            if (hh >= 0 && hh < HH && wc >= 0 && wc < WW) {
                size_t o = (size_t)hh * WW + wc;
                v = c0 * __ldg(xb + o) + c1 * __ldg(xb + NPIX + o)
                  + c2 * __ldg(xb + 2 * NPIX + o);
            }
            sgr[r][c] = v;
        }
    }
    __syncthreads();

    // ---- horizontal blur: 40 rows x 36 cols (global cols bx-2..bx+33) ----
    for (int idx = tid; idx < 1440; idx += 256) {
        int r = idx / 36, c = idx - r * 36;   // sh col c -> gray col index c+2
        sh[r][c] = w0 * sgr[r][c + 2]
                 + w1 * (sgr[r][c + 1] + sgr[r][c + 3])
                 + w2 * (sgr[r][c] + sgr[r][c + 4]);
    }
    __syncthreads();

    // ---- vertical blur: 36 rows x 36 cols into sb (col offset +2) ----
    for (int idx = tid; idx < 1296; idx += 256) {
        int r = idx / 36, c = idx - r * 36;
        sb[r][c + 2] = w0 * sh[r + 2][c]
                     + w1 * (sh[r + 1][c] + sh[r + 3][c])
                     + w2 * (sh[r][c] + sh[r + 4][c]);
    }
    __syncthreads();

    // ---- write blurred center 32x32 to global ----
    float* gb = g_blur + (size_t)b * NPIX;
    const int r0 = ty * 4;
    #pragma unroll
    for (int k = 0; k < 4; k++)
        gb[(size_t)(by + r0 + k) * WW + bx + tx] = sb[r0 + 2 + k][tx + 4];

    // ---- per-block max of s^2 on the in-smem blurred tile ----
    const int lj = tx + 4;
    float m = 0.0f;
    if (!edge) {
        float h00[4], h01[4], h11[4];
        hess4_fast(sb, r0, lj, h00, h01, h11);
        #pragma unroll
        for (int k = 0; k < 4; k++) {
            float mean = 0.5f * (h00[k] + h11[k]);
            float d    = 0.5f * (h00[k] - h11[k]);
            float q    = fmaf(d, d, h01[k] * h01[k]);
            m = fmaxf(m, 2.0f * fmaf(mean, mean, q));
        }
    } else {
        const int gj = bx + tx;
        #pragma unroll
        for (int k = 0; k < 4; k++) {
            int li = r0 + 2 + k, gi = by + r0 + k;
            float h00, h01, h11;
            hess_generic(sb, li, lj, gi, gj, h00, h01, h11);
            float mean = 0.5f * (h00 + h11);
            float d    = 0.5f * (h00 - h11);
            float q    = fmaf(d, d, h01 * h01);
            m = fmaxf(m, 2.0f * fmaf(mean, mean, q));
        }
    }

    #pragma unroll
    for (int o = 16; o; o >>= 1)
        m = fmaxf(m, __shfl_xor_sync(0xffffffffu, m, o));
    if (tx == 0) red[ty] = m;
    __syncthreads();
    if (tid == 0) {
        float mm = red[0];
        #pragma unroll
        for (int i = 1; i < 8; i++) mm = fmaxf(mm, red[i]);
        g_pmax[b * 1024 + blockIdx.y * 32 + blockIdx.x] = mm;
    }
}

// ---------------------------------------------------------------------------
// Kernel 2: gamma[b] = sqrt(max s^2)/2, one warp per batch; all-zero check.
// ---------------------------------------------------------------------------
__global__ __launch_bounds__(512) void k_gamma()
{
    __shared__ float gm[BB];
    const int w    = threadIdx.x >> 5;   // warp = batch
    const int lane = threadIdx.x & 31;

    const float* p = g_pmax + w * 1024;
    float m = 0.0f;
    #pragma unroll
    for (int i = 0; i < 32; i++)
        m = fmaxf(m, p[lane + i * 32]);
    #pragma unroll
    for (int o = 16; o; o >>= 1)
        m = fmaxf(m, __shfl_xor_sync(0xffffffffu, m, o));
    if (lane == 0) gm[w] = 0.5f * sqrtf(m);
    __syncthreads();

    if (threadIdx.x == 0) {
        bool allz = true;
        #pragma unroll
        for (int b = 0; b < BB; b++)
            if (gm[b] != 0.0f) allz = false;
        #pragma unroll
        for (int b = 0; b < BB; b++)
            g_gamma[b] = allz ? 1.0f : gm[b];
    }
}

// ---------------------------------------------------------------------------
// Response. First exp factor via MUFU (__expf, arg in [-2,0], never
// flush-critical). Second factor keeps accurate expf: the 1-exp(..)->0->1.0
// flush boundary must match the reference.
// ---------------------------------------------------------------------------
__device__ __forceinline__ float response(float h00, float h01, float h11,
                                          float inv_denom)
{
    float mean = 0.5f * (h00 + h11);
    float d    = 0.5f * (h00 - h11);
    float q    = fmaf(d, d, h01 * h01);
    float disc = sqrtf(q);
    float e0   = mean - disc;
    float e1   = mean + disc;

    float ae0 = fabsf(e0), ae1 = fabsf(e1);
    float num  = fminf(ae0, ae1);                      // |lam1|
    float lam2 = fmaxf((ae1 < ae0) ? e0 : e1, 1e-10f); // larger-|.| eig, clamped
    float rb   = __fdividef(num, lam2);

    float s2   = fmaf(e0, e0, e1 * e1);
    float vals = __expf(-2.0f * rb * rb)
               * (1.0f - expf(-s2 * inv_denom));
    return (vals <= 0.0f) ? 1.0f : vals;
}

// ---------------------------------------------------------------------------
// Kernel 3: final output from g_blur.
// Tile sg[36][44]: [r][c] = blur(clamp(by-2+r), clamp(bx-4+c)).
// ---------------------------------------------------------------------------
__global__ __launch_bounds__(256) void k_out(float* __restrict__ out)
{
    __shared__ float sg[36][44];

    const int b  = blockIdx.z;
    const int bx = blockIdx.x * 32;
    const int by = blockIdx.y * 32;
    const int tx = threadIdx.x, ty = threadIdx.y;
    const int tid = ty * 32 + tx;
    const float* gb = g_blur + (size_t)b * NPIX;

    const bool xedge = (blockIdx.x == 0) || (blockIdx.x == (WW / 32 - 1));
    const bool edge  = xedge || (blockIdx.y == 0) || (blockIdx.y == (HH / 32 - 1));

    if (!xedge) {
        for (int idx = tid; idx < 360; idx += 256) {
            int r  = idx / 10;
            int c4 = (idx - r * 10) * 4;
            int hh = min(HH - 1, max(0, by + r - 2));
            *(float4*)&sg[r][c4] =
                *(const float4*)(gb + (size_t)hh * WW + (bx - 4) + c4);
        }
    } else {
        for (int idx = tid; idx < 1440; idx += 256) {
            int r  = idx / 40;
            int c  = idx - r * 40;
            int hh = min(HH - 1, max(0, by + r - 2));
            int wc = min(WW - 1, max(0, bx - 4 + c));
            sg[r][c] = __ldg(gb + (size_t)hh * WW + wc);
        }
    }
    __syncthreads();

    const float gamma = g_gamma[b];
    const float inv_denom = 1.0f / (2.0f * gamma * gamma);
    float* ob = out + (size_t)b * NPIX;

    const int lj = tx + 4;
    const int r0 = ty * 4;

    if (!edge) {
        float h00[4], h01[4], h11[4];
        hess4_fast(sg, r0, lj, h00, h01, h11);
        #pragma unroll
        for (int k = 0; k < 4; k++) {
            ob[(size_t)(by + r0 + k) * WW + bx + tx] =
                response(h00[k], h01[k], h11[k], inv_denom);
        }
    } else {
        const int gj = bx + tx;
        #pragma unroll
        for (int k = 0; k < 4; k++) {
            int li = r0 + 2 + k, gi = by + r0 + k;
            float h00, h01, h11;
            hess_generic(sg, li, lj, gi, gj, h00, h01, h11);
            ob[(size_t)gi * WW + gj] = response(h00, h01, h11, inv_denom);
        }
    }
}

// ---------------------------------------------------------------------------
extern "C" void kernel_launch(void* const* d_in, const int* in_sizes, int n_in,
                              void* d_out, int out_size)
{
    const float* x  = (const float*)d_in[0];
    const float* tg = (const float*)d_in[1];
    if (n_in >= 2 && in_sizes[0] == 3) {  // robust to input ordering
        const float* t = x; x = tg; tg = t;
    }

    // Separable normalized Gaussian weights, L=5, sig=10.
    double e1d = exp(-0.005), e2d = exp(-0.02);
    double S = 1.0 + 2.0 * e1d + 2.0 * e2d;
    float w0 = (float)(1.0 / S);
    float w1 = (float)(e1d / S);
    float w2 = (float)(e2d / S);

    dim3 blk(32, 8);
    dim3 grd(WW / 32, HH / 32, BB);

    k_blur_smax<<<grd, blk>>>(x, tg, w0, w1, w2);
    k_gamma<<<1, 512>>>();
    k_out<<<grd, blk>>>((float*)d_out);
}

// round 16
// speedup vs baseline: 1.1596x; 1.1596x over previous
#include <cuda_runtime.h>
#include <math.h>

// Hessian_49160195670508: x [16,3,1024,1024] f32, to_gray [3] -> out [16,1024,1024]
// gray -> 5x5 gaussian blur (SAME, zero pad) -> jnp.gradient Hessian ->
// 2x2 symmetric eig -> per-batch gamma = max(s)/2 -> Frangi-like response.

#define HH 1024
#define WW 1024
#define BB 16
#define NPIX ((size_t)HH * WW)

// Static device scratch (no cudaMalloc anywhere)
__device__ float g_blur[(size_t)BB * HH * WW];   // 64 MiB blurred gray
__device__ float g_pmax[BB * 1024];              // per-block partial max of s^2
__device__ float g_gamma[BB];                    // per-batch gamma

// ---------------------------------------------------------------------------
// Generic (edge-correct) jnp.gradient stencil over a blurred tile sg[36][44]
// whose element [r][c] is blur(by-2+r, bx-4+c). Formula selection is by
// GLOBAL index, so clamped/invalid halo cells are never consumed.
// ---------------------------------------------------------------------------
__device__ __forceinline__ float sgx(const float (*sg)[44], int li, int lj, int gi)
{
    if (gi == 0)      return sg[li + 1][lj] - sg[li][lj];
    if (gi == HH - 1) return sg[li][lj] - sg[li - 1][lj];
    return 0.5f * (sg[li + 1][lj] - sg[li - 1][lj]);
}

__device__ __forceinline__ float sgy(const float (*sg)[44], int li, int lj, int gj)
{
    if (gj == 0)      return sg[li][lj + 1] - sg[li][lj];
    if (gj == WW - 1) return sg[li][lj] - sg[li][lj - 1];
    return 0.5f * (sg[li][lj + 1] - sg[li][lj - 1]);
}

__device__ __forceinline__ void hess_generic(const float (*sg)[44], int li, int lj,
                                             int gi, int gj,
                                             float& h00, float& h01, float& h11)
{
    if (gi == 0)           h00 = sgx(sg, li + 1, lj, 1) - sgx(sg, li, lj, 0);
    else if (gi == HH - 1) h00 = sgx(sg, li, lj, HH - 1) - sgx(sg, li - 1, lj, HH - 2);
    else                   h00 = 0.5f * (sgx(sg, li + 1, lj, gi + 1) - sgx(sg, li - 1, lj, gi - 1));

    if (gj == 0)           h01 = sgx(sg, li, lj + 1, gi) - sgx(sg, li, lj, gi);
    else if (gj == WW - 1) h01 = sgx(sg, li, lj, gi) - sgx(sg, li, lj - 1, gi);
    else                   h01 = 0.5f * (sgx(sg, li, lj + 1, gi) - sgx(sg, li, lj - 1, gi));

    if (gj == 0)           h11 = sgy(sg, li, lj + 1, 1) - sgy(sg, li, lj, 0);
    else if (gj == WW - 1) h11 = sgy(sg, li, lj, WW - 1) - sgy(sg, li, lj - 1, WW - 2);
    else                   h11 = 0.5f * (sgy(sg, li, lj + 1, gj + 1) - sgy(sg, li, lj - 1, gj - 1));
}

// Fast interior stencil: pure central 2nd differences, 4 consecutive rows
// per thread with register-cached columns.
__device__ __forceinline__ void hess4_fast(const float (*sg)[44], int r0, int lj,
                                           float* h00, float* h01, float* h11)
{
    float v[8], a[6], bc[6], cl[4], cr[4];
    #pragma unroll
    for (int t = 0; t < 8; t++) v[t] = sg[r0 + t][lj];
    #pragma unroll
    for (int t = 0; t < 6; t++) { a[t]  = sg[r0 + 1 + t][lj - 1];
                                  bc[t] = sg[r0 + 1 + t][lj + 1]; }
    #pragma unroll
    for (int t = 0; t < 4; t++) { cl[t] = sg[r0 + 2 + t][lj - 2];
                                  cr[t] = sg[r0 + 2 + t][lj + 2]; }
    #pragma unroll
    for (int k = 0; k < 4; k++) {
        h00[k] = 0.25f * (v[k] + v[k + 4]) - 0.5f * v[k + 2];
        h01[k] = 0.25f * ((bc[k + 2] - a[k + 2]) - (bc[k] - a[k]));
        h11[k] = 0.25f * (cl[k] + cr[k]) - 0.5f * v[k + 2];
    }
}

// ---------------------------------------------------------------------------
// Kernel 1 (FUSED): grayscale + separable 5x5 blur + write g_blur + per-block
// max of s^2.  Smem-traffic-optimized:
//   * h-blur: 4 outputs from 2x LDS.128 + 1x STS.128  (sh pitch 40 = 160B)
//   * v-blur: rolling 9-register window, 5 outputs per thread-column
//   * no div/mod in the per-element hot loops
// Gray halo: rows by-4..by+35, cols bx-4..bx+35 (zero pad outside image).
// sh[r][c]  = h-blur at (by-4+r, bx-2+c),   r<40, c<36 (pitch 40)
// sb[r][c]  = full blur at (by-2+r, bx-4+c), r<36, valid c in 2..37
// ---------------------------------------------------------------------------
__global__ __launch_bounds__(256) void k_blur_smax(
    const float* __restrict__ x, const float* __restrict__ tg,
    float w0, float w1, float w2)
{
    __shared__ float sgr[40][44];  // gray, rows by-4.., cols bx-4..bx+35 (40 used)
    __shared__ float sh[40][40];   // horiz blurred
    __shared__ float sb[36][44];   // fully blurred
    __shared__ float red[8];

    const int b  = blockIdx.z;
    const int bx = blockIdx.x * 32;
    const int by = blockIdx.y * 32;
    const int tx = threadIdx.x, ty = threadIdx.y;
    const int tid = ty * 32 + tx;

    const float c0 = __ldg(tg + 0);
    const float c1 = __ldg(tg + 1);
    const float c2 = __ldg(tg + 2);
    const float* xb = x + (size_t)b * 3 * NPIX;

    const bool xedge = (blockIdx.x == 0) || (blockIdx.x == (WW / 32 - 1));
    const bool edge  = xedge || (blockIdx.y == 0) || (blockIdx.y == (HH / 32 - 1));

    // ---- load gray halo (zero outside image: SAME conv zero-pads) ----
    if (!xedge) {
        #pragma unroll
        for (int k = 0; k < 2; k++) {
            int idx = tid + k * 256;
            if (idx < 400) {
                int r  = idx / 10;
                int c4 = (idx - r * 10) * 4;
                int hh = by + r - 4;
                float4 g4 = make_float4(0.f, 0.f, 0.f, 0.f);
                if (hh >= 0 && hh < HH) {
                    size_t o = (size_t)hh * WW + (bx - 4) + c4;
                    float4 a = *(const float4*)(xb + o);
                    float4 v = *(const float4*)(xb + NPIX + o);
                    float4 w = *(const float4*)(xb + 2 * NPIX + o);
                    g4.x = c0 * a.x + c1 * v.x + c2 * w.x;
                    g4.y = c0 * a.y + c1 * v.y + c2 * w.y;
                    g4.z = c0 * a.z + c1 * v.z + c2 * w.z;
                    g4.w = c0 * a.w + c1 * v.w + c2 * w.w;
                }
                *(float4*)&sgr[r][c4] = g4;
            }
        }
    } else {
        for (int idx = tid; idx < 1600; idx += 256) {
            int r  = idx / 40;
            int c  = idx - r * 40;
            int hh = by + r - 4;
            int wc = bx - 4 + c;
            float v = 0.f;
            if (hh >= 0 && hh < HH && wc >= 0 && wc < WW) {
                size_t o = (size_t)hh * WW + wc;
                v = c0 * __ldg(xb + o) + c1 * __ldg(xb + NPIX + o)
                  + c2 * __ldg(xb + 2 * NPIX + o);
            }
            sgr[r][c] = v;
        }
    }
    __syncthreads();

    // ---- horizontal blur: 40 rows x 9 float4 groups (36 cols) ----
    #pragma unroll
    for (int k = 0; k < 2; k++) {
        int idx = tid + k * 256;
        if (idx < 360) {
            int r  = idx / 9;
            int g  = idx - r * 9;
            int c4 = g * 4;
            float4 A = *(const float4*)&sgr[r][c4];
            float4 B = *(const float4*)&sgr[r][c4 + 4];
            float4 o;
            o.x = w0 * A.z + w1 * (A.y + A.w) + w2 * (A.x + B.x);
            o.y = w0 * A.w + w1 * (A.z + B.x) + w2 * (A.y + B.y);
            o.z = w0 * B.x + w1 * (A.w + B.y) + w2 * (A.z + B.z);
            o.w = w0 * B.y + w1 * (B.x + B.z) + w2 * (A.w + B.w);
            *(float4*)&sh[r][c4] = o;
        }
    }
    __syncthreads();

    // ---- vertical blur: rolling window, 5 output rows per thread-column ----
    {
        const int rv0 = ty * 5;            // 0,5,...,35
        // pass 1: columns 0..31
        {
            float w[9];
            #pragma unroll
            for (int t = 0; t < 9; t++) {
                int rr = rv0 + t;
                w[t] = (rr < 40) ? sh[rr][tx] : 0.f;
            }
            #pragma unroll
            for (int k = 0; k < 5; k++) {
                int r = rv0 + k;
                if (r < 36)
                    sb[r][tx + 2] = w0 * w[k + 2] + w1 * (w[k + 1] + w[k + 3])
                                  + w2 * (w[k] + w[k + 4]);
            }
        }
        // pass 2: columns 32..35
        if (tx < 4) {
            int c = 32 + tx;
            float w[9];
            #pragma unroll
            for (int t = 0; t < 9; t++) {
                int rr = rv0 + t;
                w[t] = (rr < 40) ? sh[rr][c] : 0.f;
            }
            #pragma unroll
            for (int k = 0; k < 5; k++) {
                int r = rv0 + k;
                if (r < 36)
                    sb[r][c + 2] = w0 * w[k + 2] + w1 * (w[k + 1] + w[k + 3])
                                 + w2 * (w[k] + w[k + 4]);
            }
        }
    }
    __syncthreads();

    // ---- write blurred center 32x32 to global ----
    float* gb = g_blur + (size_t)b * NPIX;
    const int r0 = ty * 4;
    #pragma unroll
    for (int k = 0; k < 4; k++)
        gb[(size_t)(by + r0 + k) * WW + bx + tx] = sb[r0 + 2 + k][tx + 4];

    // ---- per-block max of s^2 on the in-smem blurred tile ----
    const int lj = tx + 4;
    float m = 0.0f;
    if (!edge) {
        float h00[4], h01[4], h11[4];
        hess4_fast(sb, r0, lj, h00, h01, h11);
        #pragma unroll
        for (int k = 0; k < 4; k++) {
            float mean = 0.5f * (h00[k] + h11[k]);
            float d    = 0.5f * (h00[k] - h11[k]);
            float q    = fmaf(d, d, h01[k] * h01[k]);
            m = fmaxf(m, 2.0f * fmaf(mean, mean, q));
        }
    } else {
        const int gj = bx + tx;
        #pragma unroll
        for (int k = 0; k < 4; k++) {
            int li = r0 + 2 + k, gi = by + r0 + k;
            float h00, h01, h11;
            hess_generic(sb, li, lj, gi, gj, h00, h01, h11);
            float mean = 0.5f * (h00 + h11);
            float d    = 0.5f * (h00 - h11);
            float q    = fmaf(d, d, h01 * h01);
            m = fmaxf(m, 2.0f * fmaf(mean, mean, q));
        }
    }

    #pragma unroll
    for (int o = 16; o; o >>= 1)
        m = fmaxf(m, __shfl_xor_sync(0xffffffffu, m, o));
    if (tx == 0) red[ty] = m;
    __syncthreads();
    if (tid == 0) {
        float mm = red[0];
        #pragma unroll
        for (int i = 1; i < 8; i++) mm = fmaxf(mm, red[i]);
        g_pmax[b * 1024 + blockIdx.y * 32 + blockIdx.x] = mm;
    }
}

// ---------------------------------------------------------------------------
// Kernel 2: gamma[b] = sqrt(max s^2)/2, one warp per batch; all-zero check.
// ---------------------------------------------------------------------------
__global__ __launch_bounds__(512) void k_gamma()
{
    __shared__ float gm[BB];
    const int w    = threadIdx.x >> 5;   // warp = batch
    const int lane = threadIdx.x & 31;

    const float* p = g_pmax + w * 1024;
    float m = 0.0f;
    #pragma unroll
    for (int i = 0; i < 32; i++)
        m = fmaxf(m, p[lane + i * 32]);
    #pragma unroll
    for (int o = 16; o; o >>= 1)
        m = fmaxf(m, __shfl_xor_sync(0xffffffffu, m, o));
    if (lane == 0) gm[w] = 0.5f * sqrtf(m);
    __syncthreads();

    if (threadIdx.x == 0) {
        bool allz = true;
        #pragma unroll
        for (int b = 0; b < BB; b++)
            if (gm[b] != 0.0f) allz = false;
        #pragma unroll
        for (int b = 0; b < BB; b++)
            g_gamma[b] = allz ? 1.0f : gm[b];
    }
}

// ---------------------------------------------------------------------------
// Response. First exp factor via MUFU (__expf, arg in [-2,0], never
// flush-critical). Second factor keeps accurate expf: the 1-exp(..)->0->1.0
// flush boundary must match the reference.
// ---------------------------------------------------------------------------
__device__ __forceinline__ float response(float h00, float h01, float h11,
                                          float inv_denom)
{
    float mean = 0.5f * (h00 + h11);
    float d    = 0.5f * (h00 - h11);
    float q    = fmaf(d, d, h01 * h01);
    float disc = sqrtf(q);
    float e0   = mean - disc;
    float e1   = mean + disc;

    float ae0 = fabsf(e0), ae1 = fabsf(e1);
    float num  = fminf(ae0, ae1);                      // |lam1|
    float lam2 = fmaxf((ae1 < ae0) ? e0 : e1, 1e-10f); // larger-|.| eig, clamped
    float rb   = __fdividef(num, lam2);

    float s2   = fmaf(e0, e0, e1 * e1);
    float vals = __expf(-2.0f * rb * rb)
               * (1.0f - expf(-s2 * inv_denom));
    return (vals <= 0.0f) ? 1.0f : vals;
}

// ---------------------------------------------------------------------------
// Kernel 3: final output from g_blur.
// Tile sg[36][44]: [r][c] = blur(clamp(by-2+r), clamp(bx-4+c)); cols 0..39 loaded.
// ---------------------------------------------------------------------------
__global__ __launch_bounds__(256) void k_out(float* __restrict__ out)
{
    __shared__ float sg[36][44];

    const int b  = blockIdx.z;
    const int bx = blockIdx.x * 32;
    const int by = blockIdx.y * 32;
    const int tx = threadIdx.x, ty = threadIdx.y;
    const int tid = ty * 32 + tx;
    const float* gb = g_blur + (size_t)b * NPIX;

    const bool xedge = (blockIdx.x == 0) || (blockIdx.x == (WW / 32 - 1));
    const bool edge  = xedge || (blockIdx.y == 0) || (blockIdx.y == (HH / 32 - 1));

    if (!xedge) {
        #pragma unroll
        for (int k = 0; k < 2; k++) {
            int idx = tid + k * 256;
            if (idx < 360) {
                int r  = idx / 10;
                int c4 = (idx - r * 10) * 4;
                int hh = min(HH - 1, max(0, by + r - 2));
                *(float4*)&sg[r][c4] =
                    *(const float4*)(gb + (size_t)hh * WW + (bx - 4) + c4);
            }
        }
    } else {
        for (int idx = tid; idx < 1440; idx += 256) {
            int r  = idx / 40;
            int c  = idx - r * 40;
            int hh = min(HH - 1, max(0, by + r - 2));
            int wc = min(WW - 1, max(0, bx - 4 + c));
            sg[r][c] = __ldg(gb + (size_t)hh * WW + wc);
        }
    }
    __syncthreads();

    const float gamma = g_gamma[b];
    const float inv_denom = 1.0f / (2.0f * gamma * gamma);
    float* ob = out + (size_t)b * NPIX;

    const int lj = tx + 4;
    const int r0 = ty * 4;

    if (!edge) {
        float h00[4], h01[4], h11[4];
        hess4_fast(sg, r0, lj, h00, h01, h11);
        #pragma unroll
        for (int k = 0; k < 4; k++) {
            ob[(size_t)(by + r0 + k) * WW + bx + tx] =
                response(h00[k], h01[k], h11[k], inv_denom);
        }
    } else {
        const int gj = bx + tx;
        #pragma unroll
        for (int k = 0; k < 4; k++) {
            int li = r0 + 2 + k, gi = by + r0 + k;
            float h00, h01, h11;
            hess_generic(sg, li, lj, gi, gj, h00, h01, h11);
            ob[(size_t)gi * WW + gj] = response(h00, h01, h11, inv_denom);
        }
    }
}

// ---------------------------------------------------------------------------
extern "C" void kernel_launch(void* const* d_in, const int* in_sizes, int n_in,
                              void* d_out, int out_size)
{
    const float* x  = (const float*)d_in[0];
    const float* tg = (const float*)d_in[1];
    if (n_in >= 2 && in_sizes[0] == 3) {  // robust to input ordering
        const float* t = x; x = tg; tg = t;
    }

    // Separable normalized Gaussian weights, L=5, sig=10.
    double e1d = exp(-0.005), e2d = exp(-0.02);
    double S = 1.0 + 2.0 * e1d + 2.0 * e2d;
    float w0 = (float)(1.0 / S);
    float w1 = (float)(e1d / S);
    float w2 = (float)(e2d / S);

    dim3 blk(32, 8);
    dim3 grd(WW / 32, HH / 32, BB);

    k_blur_smax<<<grd, blk>>>(x, tg, w0, w1, w2);
    k_gamma<<<1, 512>>>();
    k_out<<<grd, blk>>>((float*)d_out);
}

// round 17
// speedup vs baseline: 1.3192x; 1.1377x over previous
#include <cuda_runtime.h>
#include <math.h>

// Hessian_49160195670508: x [16,3,1024,1024] f32, to_gray [3] -> out [16,1024,1024]
// gray -> 5x5 gaussian blur (SAME, zero pad) -> jnp.gradient Hessian ->
// 2x2 symmetric eig -> per-batch gamma = max(s)/2 -> Frangi-like response.
//
// Structure: k1 fuses gray+blur+Hessian+eig, emitting per-pixel
// {p = exp(-2 rb^2), s^2} plus per-block max(s^2). k_gamma reduces gamma.
// k_out is a pure stream: out = p * (1 - exp(-s^2/(2 gamma^2))).

#define HH 1024
#define WW 1024
#define BB 16
#define NPIX ((size_t)HH * WW)

// Static device scratch (no cudaMalloc anywhere)
__device__ float2 g_ps[(size_t)BB * HH * WW];    // 128 MiB: {p, s^2} per pixel
__device__ float  g_pmax[BB * 1024];             // per-block partial max of s^2
__device__ float  g_gamma[BB];                   // per-batch gamma

// ---------------------------------------------------------------------------
// Generic (edge-correct) jnp.gradient stencil over a blurred tile sg[36][44]
// whose element [r][c] is blur(by-2+r, bx-4+c). Formula selection is by
// GLOBAL index, so invalid halo cells are never consumed.
// ---------------------------------------------------------------------------
__device__ __forceinline__ float sgx(const float (*sg)[44], int li, int lj, int gi)
{
    if (gi == 0)      return sg[li + 1][lj] - sg[li][lj];
    if (gi == HH - 1) return sg[li][lj] - sg[li - 1][lj];
    return 0.5f * (sg[li + 1][lj] - sg[li - 1][lj]);
}

__device__ __forceinline__ float sgy(const float (*sg)[44], int li, int lj, int gj)
{
    if (gj == 0)      return sg[li][lj + 1] - sg[li][lj];
    if (gj == WW - 1) return sg[li][lj] - sg[li][lj - 1];
    return 0.5f * (sg[li][lj + 1] - sg[li][lj - 1]);
}

__device__ __forceinline__ void hess_generic(const float (*sg)[44], int li, int lj,
                                             int gi, int gj,
                                             float& h00, float& h01, float& h11)
{
    if (gi == 0)           h00 = sgx(sg, li + 1, lj, 1) - sgx(sg, li, lj, 0);
    else if (gi == HH - 1) h00 = sgx(sg, li, lj, HH - 1) - sgx(sg, li - 1, lj, HH - 2);
    else                   h00 = 0.5f * (sgx(sg, li + 1, lj, gi + 1) - sgx(sg, li - 1, lj, gi - 1));

    if (gj == 0)           h01 = sgx(sg, li, lj + 1, gi) - sgx(sg, li, lj, gi);
    else if (gj == WW - 1) h01 = sgx(sg, li, lj, gi) - sgx(sg, li, lj - 1, gi);
    else                   h01 = 0.5f * (sgx(sg, li, lj + 1, gi) - sgx(sg, li, lj - 1, gi));

    if (gj == 0)           h11 = sgy(sg, li, lj + 1, 1) - sgy(sg, li, lj, 0);
    else if (gj == WW - 1) h11 = sgy(sg, li, lj, WW - 1) - sgy(sg, li, lj - 1, WW - 2);
    else                   h11 = 0.5f * (sgy(sg, li, lj + 1, gj + 1) - sgy(sg, li, lj - 1, gj - 1));
}

// Fast interior stencil: pure central 2nd differences, 4 consecutive rows
// per thread with register-cached columns.
__device__ __forceinline__ void hess4_fast(const float (*sg)[44], int r0, int lj,
                                           float* h00, float* h01, float* h11)
{
    float v[8], a[6], bc[6], cl[4], cr[4];
    #pragma unroll
    for (int t = 0; t < 8; t++) v[t] = sg[r0 + t][lj];
    #pragma unroll
    for (int t = 0; t < 6; t++) { a[t]  = sg[r0 + 1 + t][lj - 1];
                                  bc[t] = sg[r0 + 1 + t][lj + 1]; }
    #pragma unroll
    for (int t = 0; t < 4; t++) { cl[t] = sg[r0 + 2 + t][lj - 2];
                                  cr[t] = sg[r0 + 2 + t][lj + 2]; }
    #pragma unroll
    for (int k = 0; k < 4; k++) {
        h00[k] = 0.25f * (v[k] + v[k + 4]) - 0.5f * v[k + 2];
        h01[k] = 0.25f * ((bc[k + 2] - a[k + 2]) - (bc[k] - a[k]));
        h11[k] = 0.25f * (cl[k] + cr[k]) - 0.5f * v[k + 2];
    }
}

// From Hessian -> p = __expf(-2 rb^2) (gamma-independent Frangi factor, in
// [exp(-2),1], never flush-critical) and s2 = e0^2 + e1^2.
__device__ __forceinline__ float2 precursor(float h00, float h01, float h11)
{
    float mean = 0.5f * (h00 + h11);
    float d    = 0.5f * (h00 - h11);
    float q    = fmaf(d, d, h01 * h01);
    float disc = sqrtf(q);
    float e0   = mean - disc;
    float e1   = mean + disc;

    float ae0 = fabsf(e0), ae1 = fabsf(e1);
    float num  = fminf(ae0, ae1);                      // |lam1|
    float lam2 = fmaxf((ae1 < ae0) ? e0 : e1, 1e-10f); // larger-|.| eig, clamped
    float rb   = __fdividef(num, lam2);

    float s2   = fmaf(e0, e0, e1 * e1);
    float p    = __expf(-2.0f * rb * rb);
    return make_float2(p, s2);
}

// ---------------------------------------------------------------------------
// Kernel 1 (FUSED): grayscale + separable 5x5 blur + Hessian + eig precursor.
// Writes g_ps[pixel] = {p, s^2} and per-block max(s^2). The blurred image
// never touches DRAM.
// Gray halo: rows by-4..by+35, cols bx-4..bx+35 (zero pad outside image).
// sh[r][c]  = h-blur at (by-4+r, bx-2+c),   r<40, c<36 (pitch 40)
// sb[r][c]  = full blur at (by-2+r, bx-4+c), r<36, valid c in 2..37
// ---------------------------------------------------------------------------
__global__ __launch_bounds__(256) void k_blur_ps(
    const float* __restrict__ x, const float* __restrict__ tg,
    float w0, float w1, float w2)
{
    __shared__ float sgr[40][44];
    __shared__ float sh[40][40];
    __shared__ float sb[36][44];
    __shared__ float red[8];

    const int b  = blockIdx.z;
    const int bx = blockIdx.x * 32;
    const int by = blockIdx.y * 32;
    const int tx = threadIdx.x, ty = threadIdx.y;
    const int tid = ty * 32 + tx;

    const float c0 = __ldg(tg + 0);
    const float c1 = __ldg(tg + 1);
    const float c2 = __ldg(tg + 2);
    const float* xb = x + (size_t)b * 3 * NPIX;

    const bool xedge = (blockIdx.x == 0) || (blockIdx.x == (WW / 32 - 1));
    const bool edge  = xedge || (blockIdx.y == 0) || (blockIdx.y == (HH / 32 - 1));

    // ---- load gray halo (zero outside image: SAME conv zero-pads) ----
    if (!xedge) {
        #pragma unroll
        for (int k = 0; k < 2; k++) {
            int idx = tid + k * 256;
            if (idx < 400) {
                int r  = idx / 10;
                int c4 = (idx - r * 10) * 4;
                int hh = by + r - 4;
                float4 g4 = make_float4(0.f, 0.f, 0.f, 0.f);
                if (hh >= 0 && hh < HH) {
                    size_t o = (size_t)hh * WW + (bx - 4) + c4;
                    float4 a = *(const float4*)(xb + o);
                    float4 v = *(const float4*)(xb + NPIX + o);
                    float4 w = *(const float4*)(xb + 2 * NPIX + o);
                    g4.x = c0 * a.x + c1 * v.x + c2 * w.x;
                    g4.y = c0 * a.y + c1 * v.y + c2 * w.y;
                    g4.z = c0 * a.z + c1 * v.z + c2 * w.z;
                    g4.w = c0 * a.w + c1 * v.w + c2 * w.w;
                }
                *(float4*)&sgr[r][c4] = g4;
            }
        }
    } else {
        for (int idx = tid; idx < 1600; idx += 256) {
            int r  = idx / 40;
            int c  = idx - r * 40;
            int hh = by + r - 4;
            int wc = bx - 4 + c;
            float v = 0.f;
            if (hh >= 0 && hh < HH && wc >= 0 && wc < WW) {
                size_t o = (size_t)hh * WW + wc;
                v = c0 * __ldg(xb + o) + c1 * __ldg(xb + NPIX + o)
                  + c2 * __ldg(xb + 2 * NPIX + o);
            }
            sgr[r][c] = v;
        }
    }
    __syncthreads();

    // ---- horizontal blur: 40 rows x 9 float4 groups (36 cols) ----
    #pragma unroll
    for (int k = 0; k < 2; k++) {
        int idx = tid + k * 256;
        if (idx < 360) {
            int r  = idx / 9;
            int g  = idx - r * 9;
            int c4 = g * 4;
            float4 A = *(const float4*)&sgr[r][c4];
            float4 B = *(const float4*)&sgr[r][c4 + 4];
            float4 o;
            o.x = w0 * A.z + w1 * (A.y + A.w) + w2 * (A.x + B.x);
            o.y = w0 * A.w + w1 * (A.z + B.x) + w2 * (A.y + B.y);
            o.z = w0 * B.x + w1 * (A.w + B.y) + w2 * (A.z + B.z);
            o.w = w0 * B.y + w1 * (B.x + B.z) + w2 * (A.w + B.w);
            *(float4*)&sh[r][c4] = o;
        }
    }
    __syncthreads();

    // ---- vertical blur: rolling window, 5 output rows per thread-column ----
    {
        const int rv0 = ty * 5;            // 0,5,...,35
        {
            float w[9];
            #pragma unroll
            for (int t = 0; t < 9; t++) {
                int rr = rv0 + t;
                w[t] = (rr < 40) ? sh[rr][tx] : 0.f;
            }
            #pragma unroll
            for (int k = 0; k < 5; k++) {
                int r = rv0 + k;
                if (r < 36)
                    sb[r][tx + 2] = w0 * w[k + 2] + w1 * (w[k + 1] + w[k + 3])
                                  + w2 * (w[k] + w[k + 4]);
            }
        }
        if (tx < 4) {
            int c = 32 + tx;
            float w[9];
            #pragma unroll
            for (int t = 0; t < 9; t++) {
                int rr = rv0 + t;
                w[t] = (rr < 40) ? sh[rr][c] : 0.f;
            }
            #pragma unroll
            for (int k = 0; k < 5; k++) {
                int r = rv0 + k;
                if (r < 36)
                    sb[r][c + 2] = w0 * w[k + 2] + w1 * (w[k + 1] + w[k + 3])
                                 + w2 * (w[k] + w[k + 4]);
            }
        }
    }
    __syncthreads();

    // ---- Hessian + eig precursor + per-block max(s^2), store {p,s^2} ----
    float2* psb = g_ps + (size_t)b * NPIX;
    const int r0 = ty * 4;
    const int lj = tx + 4;
    float m = 0.0f;

    float h00[4], h01[4], h11[4];
    if (!edge) {
        hess4_fast(sb, r0, lj, h00, h01, h11);
    } else {
        const int gj = bx + tx;
        #pragma unroll
        for (int k = 0; k < 4; k++) {
            int li = r0 + 2 + k, gi = by + r0 + k;
            hess_generic(sb, li, lj, gi, gj, h00[k], h01[k], h11[k]);
        }
    }
    #pragma unroll
    for (int k = 0; k < 4; k++) {
        float2 ps = precursor(h00[k], h01[k], h11[k]);
        m = fmaxf(m, ps.y);
        psb[(size_t)(by + r0 + k) * WW + bx + tx] = ps;
    }

    #pragma unroll
    for (int o = 16; o; o >>= 1)
        m = fmaxf(m, __shfl_xor_sync(0xffffffffu, m, o));
    if (tx == 0) red[ty] = m;
    __syncthreads();
    if (tid == 0) {
        float mm = red[0];
        #pragma unroll
        for (int i = 1; i < 8; i++) mm = fmaxf(mm, red[i]);
        g_pmax[b * 1024 + blockIdx.y * 32 + blockIdx.x] = mm;
    }
}

// ---------------------------------------------------------------------------
// Kernel 2: gamma[b] = sqrt(max s^2)/2, one warp per batch; all-zero check.
// ---------------------------------------------------------------------------
__global__ __launch_bounds__(512) void k_gamma()
{
    __shared__ float gm[BB];
    const int w    = threadIdx.x >> 5;   // warp = batch
    const int lane = threadIdx.x & 31;

    const float* p = g_pmax + w * 1024;
    float m = 0.0f;
    #pragma unroll
    for (int i = 0; i < 32; i++)
        m = fmaxf(m, p[lane + i * 32]);
    #pragma unroll
    for (int o = 16; o; o >>= 1)
        m = fmaxf(m, __shfl_xor_sync(0xffffffffu, m, o));
    if (lane == 0) gm[w] = 0.5f * sqrtf(m);
    __syncthreads();

    if (threadIdx.x == 0) {
        bool allz = true;
        #pragma unroll
        for (int b = 0; b < BB; b++)
            if (gm[b] != 0.0f) allz = false;
        #pragma unroll
        for (int b = 0; b < BB; b++)
            g_gamma[b] = allz ? 1.0f : gm[b];
    }
}

// ---------------------------------------------------------------------------
// Kernel 3: pure stream. out = p * (1 - expf(-s2 * inv_denom)); <=0 -> 1.
// Accurate expf preserved: the 1-exp(..)->0->1.0 flush boundary must match
// the reference. 2 pixels per thread via one LDG.128.
// ---------------------------------------------------------------------------
__global__ __launch_bounds__(256) void k_out(float* __restrict__ out)
{
    const int b = blockIdx.y;
    const float gamma = g_gamma[b];
    const float inv_denom = 1.0f / (2.0f * gamma * gamma);

    const size_t base = (size_t)b * NPIX + (size_t)blockIdx.x * 512 + threadIdx.x * 2;
    float4 v = *(const float4*)((const float2*)(g_ps) + base);  // {p0,s20,p1,s21}

    float v0 = v.x * (1.0f - expf(-v.y * inv_denom));
    float v1 = v.z * (1.0f - expf(-v.w * inv_denom));

    float2 o;
    o.x = (v0 <= 0.0f) ? 1.0f : v0;
    o.y = (v1 <= 0.0f) ? 1.0f : v1;
    *(float2*)(out + base) = o;
}

// ---------------------------------------------------------------------------
extern "C" void kernel_launch(void* const* d_in, const int* in_sizes, int n_in,
                              void* d_out, int out_size)
{
    const float* x  = (const float*)d_in[0];
    const float* tg = (const float*)d_in[1];
    if (n_in >= 2 && in_sizes[0] == 3) {  // robust to input ordering
        const float* t = x; x = tg; tg = t;
    }

    // Separable normalized Gaussian weights, L=5, sig=10.
    double e1d = exp(-0.005), e2d = exp(-0.02);
    double S = 1.0 + 2.0 * e1d + 2.0 * e2d;
    float w0 = (float)(1.0 / S);
    float w1 = (float)(e1d / S);
    float w2 = (float)(e2d / S);

    dim3 blk(32, 8);
    dim3 grd(WW / 32, HH / 32, BB);

    k_blur_ps<<<grd, blk>>>(x, tg, w0, w1, w2);
    k_gamma<<<1, 512>>>();
    k_out<<<dim3(NPIX / 512, BB), 256>>>((float*)d_out);
}